// round 1
// baseline (speedup 1.0000x reference)
#include <cuda_runtime.h>
#include <math_constants.h>

// Segment structure of each 336-float macro-block:
//   seg0: off   0, 9 rows x 11
//   seg1: off  99, 9 rows x 11
//   seg2: off 198, 9 rows x  8
//   seg3: off 270, 6 rows x 11
// => 33 softmax rows per macro-block, lengths 11/11/8/11.

__constant__ int c_row_off[33] = {
      0,  11,  22,  33,  44,  55,  66,  77,  88,   // seg0
     99, 110, 121, 132, 143, 154, 165, 176, 187,   // seg1
    198, 206, 214, 222, 230, 238, 246, 254, 262,   // seg2
    270, 281, 292, 303, 314, 325                   // seg3
};

__constant__ int c_row_len[33] = {
    11, 11, 11, 11, 11, 11, 11, 11, 11,
    11, 11, 11, 11, 11, 11, 11, 11, 11,
     8,  8,  8,  8,  8,  8,  8,  8,  8,
    11, 11, 11, 11, 11, 11
};

__global__ __launch_bounds__(256) void seg_softmax_kernel(
    const float* __restrict__ x, float* __restrict__ out, int total_rows)
{
    int gid = blockIdx.x * blockDim.x + threadIdx.x;
    if (gid >= total_rows) return;

    // row -> (macro-block, row-in-block); compiler lowers /33 to magic-mul
    int blk = gid / 33;
    int r   = gid - blk * 33;

    int base = blk * 336 + c_row_off[r];
    int len  = c_row_len[r];

    float v[11];
    float m = -CUDART_INF_F;
#pragma unroll
    for (int i = 0; i < 11; ++i) {
        float val = (i < len) ? __ldg(x + base + i) : -CUDART_INF_F;
        v[i] = val;
        m = fmaxf(m, val);
    }

    float s = 0.0f;
#pragma unroll
    for (int i = 0; i < 11; ++i) {
        float e = __expf(v[i] - m);   // padded lanes: exp(-inf) = 0
        v[i] = e;
        s += e;
    }

    float inv = __fdividef(1.0f, s);
#pragma unroll
    for (int i = 0; i < 11; ++i) {
        if (i < len) out[base + i] = v[i] * inv;
    }
}

extern "C" void kernel_launch(void* const* d_in, const int* in_sizes, int n_in,
                              void* d_out, int out_size)
{
    const float* x = (const float*)d_in[0];
    float* out = (float*)d_out;

    int n_elems    = in_sizes[0];
    int n_blocks   = n_elems / 336;      // macro-blocks across whole tensor
    int total_rows = n_blocks * 33;

    int threads = 256;
    int blocks  = (total_rows + threads - 1) / threads;
    seg_softmax_kernel<<<blocks, threads>>>(x, out, total_rows);
}

// round 2
// speedup vs baseline: 1.6518x; 1.6518x over previous
#include <cuda_runtime.h>
#include <math_constants.h>

// Each 336-float macro-block = 33 softmax rows:
//   seg0: off   0, 9 x 11 | seg1: off  99, 9 x 11
//   seg2: off 198, 9 x  8 | seg3: off 270, 6 x 11

__constant__ int c_row_off[33] = {
      0,  11,  22,  33,  44,  55,  66,  77,  88,
     99, 110, 121, 132, 143, 154, 165, 176, 187,
    198, 206, 214, 222, 230, 238, 246, 254, 262,
    270, 281, 292, 303, 314, 325
};

__constant__ int c_row_len[33] = {
    11, 11, 11, 11, 11, 11, 11, 11, 11,
    11, 11, 11, 11, 11, 11, 11, 11, 11,
     8,  8,  8,  8,  8,  8,  8,  8,  8,
    11, 11, 11, 11, 11, 11
};

#define MB_PER_CTA 32
#define CTA_THREADS 352   // 11 warps; 32*33=1056 rows -> exactly 3 rows/thread

__global__ __launch_bounds__(CTA_THREADS) void seg_softmax_kernel(
    const float* __restrict__ x, float* __restrict__ out, int n_mblocks)
{
    __shared__ float s[MB_PER_CTA * 336];   // 43008 B

    const int tid = threadIdx.x;
    const int mb0 = blockIdx.x * MB_PER_CTA;
    const int nmb = min(MB_PER_CTA, n_mblocks - mb0);
    const int n_f4 = nmb * (336 / 4);       // float4 count for this slab

    // ---- Stage in: contiguous float4 loads (128B-coalesced) ----
    const float4* __restrict__ xin = (const float4*)(x + (size_t)mb0 * 336);
    float4* s4 = (float4*)s;
#pragma unroll 2
    for (int i = tid; i < n_f4; i += CTA_THREADS)
        s4[i] = xin[i];
    __syncthreads();

    // ---- Per-row softmax out of smem, results written back in place ----
    const int nrows = nmb * 33;
    for (int lr = tid; lr < nrows; lr += CTA_THREADS) {
        int mb = lr / 33;
        int rr = lr - mb * 33;
        int base = mb * 336 + c_row_off[rr];
        int len  = c_row_len[rr];

        float v[11];
        float m = -CUDART_INF_F;
#pragma unroll
        for (int i = 0; i < 11; ++i) {
            float val = (i < len) ? s[base + i] : -CUDART_INF_F;
            v[i] = val;
            m = fmaxf(m, val);
        }

        float sum = 0.0f;
#pragma unroll
        for (int i = 0; i < 11; ++i) {
            float e = __expf(v[i] - m);  // padded lanes -> 0
            v[i] = e;
            sum += e;
        }

        float inv = __fdividef(1.0f, sum);
#pragma unroll
        for (int i = 0; i < 11; ++i) {
            if (i < len) s[base + i] = v[i] * inv;
        }
    }
    __syncthreads();

    // ---- Stage out: contiguous float4 stores ----
    float4* __restrict__ o4 = (float4*)(out + (size_t)mb0 * 336);
#pragma unroll 2
    for (int i = tid; i < n_f4; i += CTA_THREADS)
        o4[i] = s4[i];
}

extern "C" void kernel_launch(void* const* d_in, const int* in_sizes, int n_in,
                              void* d_out, int out_size)
{
    const float* x = (const float*)d_in[0];
    float* out = (float*)d_out;

    int n_elems   = in_sizes[0];
    int n_mblocks = n_elems / 336;

    int grid = (n_mblocks + MB_PER_CTA - 1) / MB_PER_CTA;
    seg_softmax_kernel<<<grid, CTA_THREADS>>>(x, out, n_mblocks);
}

// round 3
// speedup vs baseline: 2.0248x; 1.2258x over previous
#include <cuda_runtime.h>
#include <math_constants.h>
#include <cstdint>

// Each 336-float macro-block = 33 softmax rows:
//   seg0: off   0, 9 x 11 | seg1: off  99, 9 x 11
//   seg2: off 198, 9 x  8 | seg3: off 270, 6 x 11

__constant__ int c_row_off[33] = {
      0,  11,  22,  33,  44,  55,  66,  77,  88,
     99, 110, 121, 132, 143, 154, 165, 176, 187,
    198, 206, 214, 222, 230, 238, 246, 254, 262,
    270, 281, 292, 303, 314, 325
};

__constant__ int c_row_len[33] = {
    11, 11, 11, 11, 11, 11, 11, 11, 11,
    11, 11, 11, 11, 11, 11, 11, 11, 11,
     8,  8,  8,  8,  8,  8,  8,  8,  8,
    11, 11, 11, 11, 11, 11
};

#define MB 16                      // macro-blocks per slab
#define SLAB_F4     (MB * 84)      // 1344 float4 per slab
#define SLAB_FLOATS (MB * 336)     // 5376 floats per slab
#define THREADS 256

__device__ __forceinline__ void cp16(uint32_t saddr, const float4* g) {
    asm volatile("cp.async.cg.shared.global [%0], [%1], 16;\n"
                 :: "r"(saddr), "l"(g));
}

__global__ __launch_bounds__(THREADS) void seg_softmax_pipe(
    const float4* __restrict__ x4, float4* __restrict__ out4,
    int n_slabs, int total_f4, int n_mblocks)
{
    __shared__ float sbuf[2][SLAB_FLOATS];   // 2 x 21504 B

    const int tid = threadIdx.x;
    int slab = blockIdx.x;
    if (slab >= n_slabs) return;

    uint32_t sb_addr[2];
    sb_addr[0] = (uint32_t)__cvta_generic_to_shared(sbuf[0]);
    sb_addr[1] = (uint32_t)__cvta_generic_to_shared(sbuf[1]);

    // ---- prefetch first slab into buffer 0 ----
    {
        int base = slab * SLAB_F4;
        int cnt  = min(SLAB_F4, total_f4 - base);
        for (int i = tid; i < cnt; i += THREADS)
            cp16(sb_addr[0] + i * 16, x4 + base + i);
        asm volatile("cp.async.commit_group;\n");
    }

    int cur = 0;
    for (; slab < n_slabs; slab += gridDim.x) {
        int next = slab + gridDim.x;
        bool have_next = next < n_slabs;

        // ---- async prefetch of next slab into the other buffer ----
        if (have_next) {
            int base = next * SLAB_F4;
            int cnt  = min(SLAB_F4, total_f4 - base);
            for (int i = tid; i < cnt; i += THREADS)
                cp16(sb_addr[cur ^ 1] + i * 16, x4 + base + i);
            asm volatile("cp.async.commit_group;\n");
            asm volatile("cp.async.wait_group 1;\n");   // current slab's group done
        } else {
            asm volatile("cp.async.wait_group 0;\n");
        }
        __syncthreads();

        // ---- ragged softmax out of smem, in place ----
        float* s = sbuf[cur];
        int base_mb = slab * MB;
        int nmb     = min(MB, n_mblocks - base_mb);
        int nrows   = nmb * 33;

        for (int lr = tid; lr < nrows; lr += THREADS) {
            int mb = lr / 33;
            int rr = lr - mb * 33;
            int rowbase = mb * 336 + c_row_off[rr];
            int len     = c_row_len[rr];

            float v[11];
            float m = -CUDART_INF_F;
#pragma unroll
            for (int i = 0; i < 11; ++i) {
                float val = (i < len) ? s[rowbase + i] : -CUDART_INF_F;
                v[i] = val;
                m = fmaxf(m, val);
            }

            float sum = 0.0f;
#pragma unroll
            for (int i = 0; i < 11; ++i) {
                float e = __expf(v[i] - m);   // padded lanes -> 0
                v[i] = e;
                sum += e;
            }

            float inv = __fdividef(1.0f, sum);
#pragma unroll
            for (int i = 0; i < 11; ++i) {
                if (i < len) s[rowbase + i] = v[i] * inv;
            }
        }
        __syncthreads();

        // ---- stage out: contiguous float4 stores ----
        {
            int base = slab * SLAB_F4;
            int cnt  = min(SLAB_F4, total_f4 - base);
            const float4* s4 = (const float4*)sbuf[cur];
            for (int i = tid; i < cnt; i += THREADS)
                out4[base + i] = s4[i];
        }
        __syncthreads();   // buffer fully drained before next iter prefetches into it

        cur ^= 1;
    }
}

extern "C" void kernel_launch(void* const* d_in, const int* in_sizes, int n_in,
                              void* d_out, int out_size)
{
    const float4* x4  = (const float4*)d_in[0];
    float4*       o4  = (float4*)d_out;

    int n_elems   = in_sizes[0];
    int n_mblocks = n_elems / 336;
    int total_f4  = n_elems / 4;
    int n_slabs   = (n_mblocks + MB - 1) / MB;

    // persistent grid: ~5 CTAs per SM on GB300 (152 SMs)
    int grid = 152 * 5;
    if (grid > n_slabs) grid = n_slabs;

    seg_softmax_pipe<<<grid, THREADS>>>(x4, o4, n_slabs, total_f4, n_mblocks);
}